// round 10
// baseline (speedup 1.0000x reference)
#include <cuda_runtime.h>
#include <math.h>

#define BNI 0.9999950000374997f   // 1/sqrt(1+1e-5)

// ---------------- scratch (device globals; identical set to Round 1) -------
__device__ float g_h1[64 * 16 * 128 * 128];
__device__ float g_h2[64 * 32 * 64 * 64];
__device__ float g_h3[64 * 64 * 32 * 32];
__device__ float g_u [64 * 2048 * 8];
__device__ float g_uhat[64 * 2048 * 48];
__device__ float g_pool[64 * 64];
__device__ float g_gate[64 * 64];

// ---------------- cp.async helpers -----------------------------------------
__device__ __forceinline__ unsigned int s2u(const void* p) {
    return (unsigned int)__cvta_generic_to_shared(p);
}
__device__ __forceinline__ void cpa4(unsigned int d, const float* s, bool ok) {
    int n = ok ? 4 : 0;
    asm volatile("cp.async.ca.shared.global [%0], [%1], 4, %2;" :: "r"(d), "l"(s), "r"(n));
}
__device__ __forceinline__ void cp_commit() { asm volatile("cp.async.commit_group;"); }
template<int N> __device__ __forceinline__ void cp_wait() {
    asm volatile("cp.async.wait_group %0;" :: "n"(N));
}

// row-granular input tile copy: NCI planes of TH x TW window.
// one thread per (ci,ry) row; rx loop unrolled (smem offs immediate).
template<int NCI, int TH, int TW, int H, int W>
__device__ __forceinline__ void cpin_rows(int tid, unsigned int din,
                                          const float* __restrict__ src,
                                          int iy0, int ix0) {
    const int NROWS = NCI * TH;
    for (int rid = tid; rid < NROWS; rid += 256) {
        int ci = rid / TH, ry = rid - ci * TH;
        int gy = iy0 + ry;
        bool oky = (gy >= 0) & (gy < H);
        const float* srow = src + ci * (H * W) + (oky ? gy : 0) * W;
        unsigned int d = din + rid * (TW * 4);
#pragma unroll
        for (int rx = 0; rx < TW; rx++) {
            int gx = ix0 + rx;
            bool ok = oky & (gx >= 0) & (gx < W);
            cpa4(d + rx * 4, srow + (ok ? gx : 0), ok);
        }
    }
}

// row-granular weight copy, 12-padded: dst [ci_l][co][12]; src [co][CIT][9].
// one thread per (ci_l,co) pair; k loop unrolled (pad predicate compile-time).
template<int NCO, int CIT>
__device__ __forceinline__ void cpw_rows(int tid, unsigned int dw,
                                         const float* __restrict__ wbase, int ci0) {
    const int NP = NCO * 4;
    for (int p = tid; p < NP; p += 256) {
        int ci_l = p / NCO, co = p - ci_l * NCO;       // NCO pow2 -> shifts
        const float* s = wbase + co * (CIT * 9) + (ci0 + ci_l) * 9;
        unsigned int d = dw + p * 48;
#pragma unroll
        for (int k = 0; k < 12; k++)
            cpa4(d + k * 4, s + (k < 9 ? k : 0), k < 9);
    }
}

// ---------------- conv1: 1->16, stride 1, pad 1, BN+ReLU -------------------
__global__ void conv1_kernel(const float* __restrict__ x,
                             const float* __restrict__ w,
                             const float* __restrict__ bg,
                             const float* __restrict__ bb) {
    __shared__ float tile[18 * 18];
    __shared__ __align__(16) float ws[16 * 12];
    __shared__ float sc[16], bi[16];
    int b = blockIdx.z, ty = blockIdx.y, tx = blockIdx.x;
    int tid = threadIdx.y * 16 + threadIdx.x;
    if (tid < 144) { int c = tid / 9, k = tid % 9; ws[c * 12 + k] = w[tid]; }
    if (tid < 16)  { sc[tid] = bg[tid] * BNI; bi[tid] = bb[tid]; }
    const float* xb = x + b * 16384;
    int oy0 = ty * 16, ox0 = tx * 16;
    for (int idx = tid; idx < 324; idx += 256) {
        int ry = idx / 18, rx = idx % 18;
        int gy = oy0 - 1 + ry, gx = ox0 - 1 + rx;
        tile[idx] = (gy >= 0 && gy < 128 && gx >= 0 && gx < 128) ? xb[gy * 128 + gx] : 0.f;
    }
    __syncthreads();
    int py = threadIdx.y, px = threadIdx.x;
    float r[9];
#pragma unroll
    for (int dy = 0; dy < 3; dy++)
#pragma unroll
        for (int dx = 0; dx < 3; dx++)
            r[dy * 3 + dx] = tile[(py + dy) * 18 + px + dx];
    int ho = oy0 + py, wo = ox0 + px;
    float* out = g_h1 + (size_t)b * 16 * 16384 + ho * 128 + wo;
#pragma unroll
    for (int c = 0; c < 16; c++) {
        const float4* wv = (const float4*)(ws + c * 12);
        float4 w0 = wv[0], w1 = wv[1], w2 = wv[2];
        float v = w0.x * r[0] + w0.y * r[1] + w0.z * r[2] + w0.w * r[3]
                + w1.x * r[4] + w1.y * r[5] + w1.z * r[6] + w1.w * r[7]
                + w2.x * r[8];
        out[c * 16384] = fmaxf(v * sc[c] + bi[c], 0.f);
    }
}

// ---------------- SE pooling: mean over HW per (b,c) -----------------------
__global__ void pool_kernel(int stage) {
    const float* src; int HW; float inv;
    if (stage == 1)      { src = g_h1; HW = 16384; inv = 1.f / 16384.f; }
    else if (stage == 2) { src = g_h2; HW = 4096;  inv = 1.f / 4096.f; }
    else                 { src = g_h3; HW = 1024;  inv = 1.f / 1024.f; }
    int bc = blockIdx.x;
    const float* p = src + (size_t)bc * HW;
    float sum = 0.f;
    for (int i = threadIdx.x; i < HW; i += 256) sum += p[i];
    __shared__ float wp[8];
#pragma unroll
    for (int o = 16; o; o >>= 1) sum += __shfl_xor_sync(~0u, sum, o);
    if ((threadIdx.x & 31) == 0) wp[threadIdx.x >> 5] = sum;
    __syncthreads();
    if (threadIdx.x == 0) {
        float t = 0.f;
#pragma unroll
        for (int w = 0; w < 8; w++) t += wp[w];
        g_pool[bc] = t * inv;
    }
}

// ---------------- SE gate (tiny MLP) per batch -----------------------------
__global__ void gate_kernel(const float* __restrict__ w1, const float* __restrict__ b1,
                            const float* __restrict__ w2, const float* __restrict__ b2,
                            int C, int K) {
    int b = blockIdx.x, c = threadIdx.x;
    __shared__ float y[64], hid[8];
    y[c] = g_pool[b * C + c];
    __syncthreads();
    if (c < K) {
        float t = b1[c];
        for (int j = 0; j < C; j++) t += w1[c * C + j] * y[j];
        hid[c] = fmaxf(t, 0.f);
    }
    __syncthreads();
    float t = b2[c];
    for (int k = 0; k < K; k++) t += w2[c * K + k] * hid[k];
    g_gate[b * C + c] = 1.f / (1.f + expf(-t));
}

// ---------------- conv2: 16->32, s2, pad1, BN+ReLU, gated in compute -------
__global__ void __launch_bounds__(256) conv2_kernel(const float* __restrict__ w,
                                                    const float* __restrict__ bg,
                                                    const float* __restrict__ bb) {
    __shared__ float sin[2][4 * 1089];
    __shared__ __align__(16) float ws[2][1536];
    __shared__ float sc[32], bi[32], sg[16];
    int b = blockIdx.z, ty = blockIdx.y, tx = blockIdx.x;
    int tid = threadIdx.x;
    if (tid < 32) { sc[tid] = bg[tid] * BNI; bi[tid] = bb[tid]; }
    if (tid < 16) sg[tid] = g_gate[b * 16 + tid];
    int cg = tid >> 7, s = tid & 127;
    int row = s >> 3, c8 = s & 7;
    int iy0 = ty * 32 - 1, ix0 = tx * 32 - 1;
    const float* src = g_h1 + (size_t)b * 16 * 16384;

    float acc[32];
#pragma unroll
    for (int k = 0; k < 32; k++) acc[k] = 0.f;

    cpw_rows<32, 16>(tid, s2u(&ws[0][0]), w, 0);
    cpin_rows<4, 33, 33, 128, 128>(tid, s2u(&sin[0][0]), src, iy0, ix0);
    cp_commit();

    for (int ch = 0; ch < 4; ch++) {
        int buf = ch & 1;
        cp_wait<0>();
        __syncthreads();
        if (ch < 3) {
            int nb = buf ^ 1;
            cpw_rows<32, 16>(tid, s2u(&ws[nb][0]), w, (ch + 1) * 4);
            cpin_rows<4, 33, 33, 128, 128>(tid, s2u(&sin[nb][0]), src + (ch + 1) * 4 * 16384, iy0, ix0);
            cp_commit();
        }
#pragma unroll
        for (int ci = 0; ci < 4; ci++) {
            float g = sg[ch * 4 + ci];
            float rin[15];
            const float* ip = &sin[buf][ci * 1089 + (2 * row) * 33 + 4 * c8];
#pragma unroll
            for (int dy = 0; dy < 3; dy++)
#pragma unroll
                for (int dx = 0; dx < 5; dx++)
                    rin[dy * 5 + dx] = ip[dy * 33 + dx] * g;
            const float4* wp = (const float4*)&ws[buf][(ci * 32 + cg * 16) * 12];
#pragma unroll
            for (int co = 0; co < 16; co++) {
                float4 w0 = wp[co * 3], w1 = wp[co * 3 + 1], w2 = wp[co * 3 + 2];
                acc[co * 2]     += w0.x * rin[0]  + w0.y * rin[1]  + w0.z * rin[2]
                                 + w0.w * rin[5]  + w1.x * rin[6]  + w1.y * rin[7]
                                 + w1.z * rin[10] + w1.w * rin[11] + w2.x * rin[12];
                acc[co * 2 + 1] += w0.x * rin[2]  + w0.y * rin[3]  + w0.z * rin[4]
                                 + w0.w * rin[7]  + w1.x * rin[8]  + w1.y * rin[9]
                                 + w1.z * rin[12] + w1.w * rin[13] + w2.x * rin[14];
            }
        }
    }
    int ho = ty * 16 + row, wo = tx * 16 + 2 * c8;
    float* out = g_h2 + (size_t)b * 32 * 4096 + ho * 64 + wo;
#pragma unroll
    for (int co = 0; co < 16; co++) {
        int cog = cg * 16 + co;
        out[cog * 4096]     = fmaxf(acc[co * 2]     * sc[cog] + bi[cog], 0.f);
        out[cog * 4096 + 1] = fmaxf(acc[co * 2 + 1] * sc[cog] + bi[cog], 0.f);
    }
}

// ---------------- conv3: 32->64, s2, pad1, BN+ReLU, gated in compute -------
__global__ void __launch_bounds__(256) conv3_kernel(const float* __restrict__ w,
                                                    const float* __restrict__ bg,
                                                    const float* __restrict__ bb) {
    __shared__ float sin[2][4 * 561];
    __shared__ __align__(16) float ws[2][3072];
    __shared__ float sc[64], bi[64], sg[32];
    int b = blockIdx.z, ty = blockIdx.y, tx = blockIdx.x;
    int tid = threadIdx.x;
    if (tid < 64) { sc[tid] = bg[tid] * BNI; bi[tid] = bb[tid]; }
    if (tid < 32) sg[tid] = g_gate[b * 32 + tid];
    int cg = tid >> 6, s = tid & 63;
    int row = s >> 2, c4 = s & 3;
    int iy0 = ty * 32 - 1, ix0 = tx * 16 - 1;
    const float* src = g_h2 + (size_t)b * 32 * 4096;

    float acc[32];
#pragma unroll
    for (int k = 0; k < 32; k++) acc[k] = 0.f;

    cpw_rows<64, 32>(tid, s2u(&ws[0][0]), w, 0);
    cpin_rows<4, 33, 17, 64, 64>(tid, s2u(&sin[0][0]), src, iy0, ix0);
    cp_commit();

    for (int ch = 0; ch < 8; ch++) {
        int buf = ch & 1;
        cp_wait<0>();
        __syncthreads();
        if (ch < 7) {
            int nb = buf ^ 1;
            cpw_rows<64, 32>(tid, s2u(&ws[nb][0]), w, (ch + 1) * 4);
            cpin_rows<4, 33, 17, 64, 64>(tid, s2u(&sin[nb][0]), src + (ch + 1) * 4 * 4096, iy0, ix0);
            cp_commit();
        }
#pragma unroll
        for (int ci = 0; ci < 4; ci++) {
            float g = sg[ch * 4 + ci];
            float rin[15];
            const float* ip = &sin[buf][ci * 561 + (2 * row) * 17 + 4 * c4];
#pragma unroll
            for (int dy = 0; dy < 3; dy++)
#pragma unroll
                for (int dx = 0; dx < 5; dx++)
                    rin[dy * 5 + dx] = ip[dy * 17 + dx] * g;
            const float4* wp = (const float4*)&ws[buf][(ci * 64 + cg * 16) * 12];
#pragma unroll
            for (int co = 0; co < 16; co++) {
                float4 w0 = wp[co * 3], w1 = wp[co * 3 + 1], w2 = wp[co * 3 + 2];
                acc[co * 2]     += w0.x * rin[0]  + w0.y * rin[1]  + w0.z * rin[2]
                                 + w0.w * rin[5]  + w1.x * rin[6]  + w1.y * rin[7]
                                 + w1.z * rin[10] + w1.w * rin[11] + w2.x * rin[12];
                acc[co * 2 + 1] += w0.x * rin[2]  + w0.y * rin[3]  + w0.z * rin[4]
                                 + w0.w * rin[7]  + w1.x * rin[8]  + w1.y * rin[9]
                                 + w1.z * rin[12] + w1.w * rin[13] + w2.x * rin[14];
            }
        }
    }
    int ho = ty * 16 + row, wo = tx * 8 + 2 * c4;
#pragma unroll
    for (int co = 0; co < 16; co++) {
        int cog = cg * 16 + co;
        float* out = g_h3 + ((size_t)b * 64 + cog) * 1024 + ho * 32 + wo;
        out[0] = fmaxf(acc[co * 2]     * sc[cog] + bi[cog], 0.f);
        out[1] = fmaxf(acc[co * 2 + 1] * sc[cog] + bi[cog], 0.f);
    }
}

// ------ primary caps: 64->64, s2, pad1, +bias, gated in compute, squash ----
__global__ void __launch_bounds__(256) pc_kernel(const float* __restrict__ w,
                                                 const float* __restrict__ pb) {
    __shared__ float sin[2][4 * 1089];
    __shared__ __align__(16) float ws[2][1536];
    __shared__ float sbias[32], sg[64];
    int H = blockIdx.x, b = blockIdx.y;
    int tid = threadIdx.x;
    if (tid < 32) sbias[tid] = pb[H * 32 + tid];
    if (tid < 64) sg[tid] = g_gate[b * 64 + tid];
    int cg = tid >> 7, s = tid & 127;
    int row = s >> 3, c8 = s & 7;
    const float* src = g_h3 + (size_t)b * 64 * 1024;
    const float* wbase = w + (size_t)(H * 32) * 576;   // [co_l][64][9]

    float acc[32];
#pragma unroll
    for (int k = 0; k < 32; k++) acc[k] = 0.f;

    cpw_rows<32, 64>(tid, s2u(&ws[0][0]), wbase, 0);
    cpin_rows<4, 33, 33, 32, 32>(tid, s2u(&sin[0][0]), src, -1, -1);
    cp_commit();

    for (int ch = 0; ch < 16; ch++) {
        int buf = ch & 1;
        cp_wait<0>();
        __syncthreads();
        if (ch < 15) {
            int nb = buf ^ 1;
            cpw_rows<32, 64>(tid, s2u(&ws[nb][0]), wbase, (ch + 1) * 4);
            cpin_rows<4, 33, 33, 32, 32>(tid, s2u(&sin[nb][0]), src + (ch + 1) * 4 * 1024, -1, -1);
            cp_commit();
        }
#pragma unroll
        for (int ci = 0; ci < 4; ci++) {
            float g = sg[ch * 4 + ci];
            float rin[15];
            const float* ip = &sin[buf][ci * 1089 + (2 * row) * 33 + 4 * c8];
#pragma unroll
            for (int dy = 0; dy < 3; dy++)
#pragma unroll
                for (int dx = 0; dx < 5; dx++)
                    rin[dy * 5 + dx] = ip[dy * 33 + dx] * g;
            const float4* wp = (const float4*)&ws[buf][(ci * 32 + cg * 16) * 12];
#pragma unroll
            for (int co = 0; co < 16; co++) {
                float4 w0 = wp[co * 3], w1 = wp[co * 3 + 1], w2 = wp[co * 3 + 2];
                acc[co * 2]     += w0.x * rin[0]  + w0.y * rin[1]  + w0.z * rin[2]
                                 + w0.w * rin[5]  + w1.x * rin[6]  + w1.y * rin[7]
                                 + w1.z * rin[10] + w1.w * rin[11] + w2.x * rin[12];
                acc[co * 2 + 1] += w0.x * rin[2]  + w0.y * rin[3]  + w0.z * rin[4]
                                 + w0.w * rin[7]  + w1.x * rin[8]  + w1.y * rin[9]
                                 + w1.z * rin[12] + w1.w * rin[13] + w2.x * rin[14];
            }
        }
    }
#pragma unroll
    for (int co = 0; co < 16; co++) {
        float bsv = sbias[cg * 16 + co];
        acc[co * 2] += bsv; acc[co * 2 + 1] += bsv;
    }
    // co_glob = H*32 + cg*16 + 8a + e ; a0 = H*4 + cg*2 + a
#pragma unroll
    for (int a = 0; a < 2; a++)
#pragma unroll
        for (int px = 0; px < 2; px++) {
            float n2 = 0.f;
#pragma unroll
            for (int e = 0; e < 8; e++) {
                float v = acc[(a * 8 + e) * 2 + px];
                n2 += v * v;
            }
            float f = (n2 / (1.f + n2)) / (sqrtf(n2) + 1e-8f);
            int i = (H * 4 + cg * 2 + a) * 256 + row * 16 + 2 * c8 + px;
            float* up = g_u + ((size_t)b * 2048 + i) * 8;
#pragma unroll
            for (int e = 0; e < 8; e++)
                up[e] = acc[(a * 8 + e) * 2 + px] * f;
        }
}

// ---------------- u_hat[b,i,c,d] = sum_e W[i,c,d,e] * u[b,i,e] -------------
__global__ void uhat_kernel(const float* __restrict__ W) {
    int idx = blockIdx.x * 256 + threadIdx.x;
    int b = idx / 98304;
    int r = idx - b * 98304;
    int i = r / 48;
    const float4* wp = (const float4*)(W + (size_t)r * 8);
    const float4* up = (const float4*)(g_u + ((size_t)b * 2048 + i) * 8);
    float4 w0 = wp[0], w1 = wp[1], u0 = up[0], u1 = up[1];
    g_uhat[idx] = w0.x * u0.x + w0.y * u0.y + w0.z * u0.z + w0.w * u0.w
                + w1.x * u1.x + w1.y * u1.y + w1.z * u1.z + w1.w * u1.w;
}

// ---------------- dynamic routing (exact Round-1 version) ------------------
__device__ __forceinline__ void reduce_squash(float* sacc, float mult,
                                              float* s, float* v, float* wpart,
                                              int tid, int lane, int wid) {
#pragma unroll
    for (int k = 0; k < 48; k++) {
        float x = sacc[k];
#pragma unroll
        for (int o = 16; o; o >>= 1) x += __shfl_xor_sync(~0u, x, o);
        if (lane == 0) wpart[wid * 48 + k] = x;
    }
    __syncthreads();
    if (tid < 48) {
        float t = 0.f;
#pragma unroll
        for (int w = 0; w < 8; w++) t += wpart[w * 48 + tid];
        s[tid] = t * mult;
    }
    __syncthreads();
    if (tid < 3) {
        float n2 = 0.f;
#pragma unroll
        for (int d = 0; d < 16; d++) n2 += s[tid * 16 + d] * s[tid * 16 + d];
        float f = (n2 / (1.f + n2)) / (sqrtf(n2) + 1e-8f);
#pragma unroll
        for (int d = 0; d < 16; d++) v[tid * 16 + d] = s[tid * 16 + d] * f;
    }
    __syncthreads();
}

__global__ void __launch_bounds__(256) routing_kernel(float* __restrict__ out) {
    __shared__ float bl[2048 * 3];
    __shared__ float s[48], v[48];
    __shared__ float wpart[8 * 48];
    int b = blockIdx.x, tid = threadIdx.x, lane = tid & 31, wid = tid >> 5;
    const float* uh_b = g_uhat + (size_t)b * 98304;
    for (int idx = tid; idx < 6144; idx += 256) bl[idx] = 0.f;
    __syncthreads();

    float sacc[48];
#pragma unroll
    for (int k = 0; k < 48; k++) sacc[k] = 0.f;
    for (int r = 0; r < 8; r++) {
        int i = r * 256 + tid;
        const float4* p = (const float4*)(uh_b + i * 48);
#pragma unroll
        for (int q = 0; q < 12; q++) {
            float4 t = p[q];
            sacc[4 * q] += t.x; sacc[4 * q + 1] += t.y;
            sacc[4 * q + 2] += t.z; sacc[4 * q + 3] += t.w;
        }
    }
    reduce_squash(sacc, 1.f / 3.f, s, v, wpart, tid, lane, wid);

    for (int it = 1; it < 3; it++) {
#pragma unroll
        for (int k = 0; k < 48; k++) sacc[k] = 0.f;
        for (int r = 0; r < 8; r++) {
            int i = r * 256 + tid;
            const float4* p = (const float4*)(uh_b + i * 48);
            float uh[48];
#pragma unroll
            for (int q = 0; q < 12; q++) {
                float4 t = p[q];
                uh[4 * q] = t.x; uh[4 * q + 1] = t.y;
                uh[4 * q + 2] = t.z; uh[4 * q + 3] = t.w;
            }
            float a0 = 0.f, a1 = 0.f, a2 = 0.f;
#pragma unroll
            for (int d = 0; d < 16; d++) {
                a0 += uh[d] * v[d];
                a1 += uh[16 + d] * v[16 + d];
                a2 += uh[32 + d] * v[32 + d];
            }
            float b0 = bl[i * 3] + a0, b1 = bl[i * 3 + 1] + a1, b2 = bl[i * 3 + 2] + a2;
            bl[i * 3] = b0; bl[i * 3 + 1] = b1; bl[i * 3 + 2] = b2;
            float m = fmaxf(b0, fmaxf(b1, b2));
            float e0 = expf(b0 - m), e1 = expf(b1 - m), e2 = expf(b2 - m);
            float inv = 1.f / (e0 + e1 + e2);
            e0 *= inv; e1 *= inv; e2 *= inv;
#pragma unroll
            for (int d = 0; d < 16; d++) {
                sacc[d]      += e0 * uh[d];
                sacc[16 + d] += e1 * uh[16 + d];
                sacc[32 + d] += e2 * uh[32 + d];
            }
        }
        reduce_squash(sacc, 1.f, s, v, wpart, tid, lane, wid);
    }

    if (tid < 3) {
        float n2 = 0.f;
#pragma unroll
        for (int d = 0; d < 16; d++) n2 += v[tid * 16 + d] * v[tid * 16 + d];
        out[b * 3 + tid] = sqrtf(n2);
    }
}

// ---------------------------------------------------------------------------
extern "C" void kernel_launch(void* const* d_in, const int* in_sizes, int n_in,
                              void* d_out, int out_size) {
    const float* x       = (const float*)d_in[0];
    const float* conv1_w = (const float*)d_in[1];
    const float* bn1_g   = (const float*)d_in[2];
    const float* bn1_b   = (const float*)d_in[3];
    const float* se1_w1  = (const float*)d_in[4];
    const float* se1_b1  = (const float*)d_in[5];
    const float* se1_w2  = (const float*)d_in[6];
    const float* se1_b2  = (const float*)d_in[7];
    const float* conv2_w = (const float*)d_in[8];
    const float* bn2_g   = (const float*)d_in[9];
    const float* bn2_b   = (const float*)d_in[10];
    const float* se2_w1  = (const float*)d_in[11];
    const float* se2_b1  = (const float*)d_in[12];
    const float* se2_w2  = (const float*)d_in[13];
    const float* se2_b2  = (const float*)d_in[14];
    const float* conv3_w = (const float*)d_in[15];
    const float* bn3_g   = (const float*)d_in[16];
    const float* bn3_b   = (const float*)d_in[17];
    const float* se3_w1  = (const float*)d_in[18];
    const float* se3_b1  = (const float*)d_in[19];
    const float* se3_w2  = (const float*)d_in[20];
    const float* se3_b2  = (const float*)d_in[21];
    const float* pc_w    = (const float*)d_in[22];
    const float* pc_b    = (const float*)d_in[23];
    const float* W_digit = (const float*)d_in[24];
    float* out = (float*)d_out;

    conv1_kernel<<<dim3(8, 8, 64), dim3(16, 16)>>>(x, conv1_w, bn1_g, bn1_b);
    pool_kernel<<<64 * 16, 256>>>(1);
    gate_kernel<<<64, 16>>>(se1_w1, se1_b1, se1_w2, se1_b2, 16, 1);
    conv2_kernel<<<dim3(4, 4, 64), 256>>>(conv2_w, bn2_g, bn2_b);
    pool_kernel<<<64 * 32, 256>>>(2);
    gate_kernel<<<64, 32>>>(se2_w1, se2_b1, se2_w2, se2_b2, 32, 2);
    conv3_kernel<<<dim3(4, 2, 64), 256>>>(conv3_w, bn3_g, bn3_b);
    pool_kernel<<<64 * 64, 256>>>(3);
    gate_kernel<<<64, 64>>>(se3_w1, se3_b1, se3_w2, se3_b2, 64, 4);
    pc_kernel<<<dim3(2, 64), 256>>>(pc_w, pc_b);
    uhat_kernel<<<24576, 256>>>(W_digit);
    routing_kernel<<<64, 256>>>(out);
}

// round 11
// speedup vs baseline: 1.0038x; 1.0038x over previous
#include <cuda_runtime.h>
#include <math.h>

#define BNI 0.9999950000374997f   // 1/sqrt(1+1e-5)

// ---------------- scratch (device globals; identical set to Round 1) -------
__device__ float g_h1[64 * 16 * 128 * 128];
__device__ float g_h2[64 * 32 * 64 * 64];
__device__ float g_h3[64 * 64 * 32 * 32];
__device__ float g_u [64 * 2048 * 8];
__device__ float g_uhat[64 * 2048 * 48];
__device__ float g_pool[64 * 64];
__device__ float g_gate[64 * 64];

// ---------------- cp.async helpers -----------------------------------------
__device__ __forceinline__ unsigned int s2u(const void* p) {
    return (unsigned int)__cvta_generic_to_shared(p);
}
__device__ __forceinline__ void cpa4(unsigned int d, const float* s, bool ok) {
    int n = ok ? 4 : 0;
    asm volatile("cp.async.ca.shared.global [%0], [%1], 4, %2;" :: "r"(d), "l"(s), "r"(n));
}
__device__ __forceinline__ void cp_commit() { asm volatile("cp.async.commit_group;"); }
template<int N> __device__ __forceinline__ void cp_wait() {
    asm volatile("cp.async.wait_group %0;" :: "n"(N));
}

// row-granular input tile copy: NCI planes of TH x TW window.
// one thread per (ci,ry) row; rx loop NOT unrolled -> 1 live address reg.
template<int NCI, int TH, int TW, int H, int W>
__device__ __forceinline__ void cpin_rows(int tid, unsigned int din,
                                          const float* __restrict__ src,
                                          int iy0, int ix0) {
    const int NROWS = NCI * TH;
    for (int rid = tid; rid < NROWS; rid += 256) {
        int ci = rid / TH, ry = rid - ci * TH;
        int gy = iy0 + ry;
        bool oky = (gy >= 0) & (gy < H);
        const float* srow = src + ci * (H * W) + (oky ? gy : 0) * W + ix0;
        unsigned int d = din + rid * (TW * 4);
#pragma unroll 1
        for (int rx = 0; rx < TW; rx++) {
            int gx = ix0 + rx;
            bool ok = oky & (gx >= 0) & (gx < W);
            cpa4(d + rx * 4, ok ? (srow + rx) : src, ok);
        }
    }
}

// weight copy, 12-padded: dst [ci_l][co][12]; src [co][CIT][9].
// one thread per (ci_l,co) pair; 12-iter loop unrolled (only 1 addr base).
template<int NCO, int CIT>
__device__ __forceinline__ void cpw_rows(int tid, unsigned int dw,
                                         const float* __restrict__ wbase, int ci0) {
    const int NP = NCO * 4;
    for (int p = tid; p < NP; p += 256) {
        int ci_l = p / NCO, co = p - ci_l * NCO;       // NCO pow2 -> shifts
        const float* s = wbase + co * (CIT * 9) + (ci0 + ci_l) * 9;
        unsigned int d = dw + p * 48;
#pragma unroll
        for (int k = 0; k < 12; k++)
            cpa4(d + k * 4, s + (k < 9 ? k : 0), k < 9);
    }
}

// ---------------- conv1: 1->16, stride 1, pad 1, BN+ReLU -------------------
__global__ void conv1_kernel(const float* __restrict__ x,
                             const float* __restrict__ w,
                             const float* __restrict__ bg,
                             const float* __restrict__ bb) {
    __shared__ float tile[18 * 18];
    __shared__ __align__(16) float ws[16 * 12];
    __shared__ float sc[16], bi[16];
    int b = blockIdx.z, ty = blockIdx.y, tx = blockIdx.x;
    int tid = threadIdx.y * 16 + threadIdx.x;
    if (tid < 144) { int c = tid / 9, k = tid % 9; ws[c * 12 + k] = w[tid]; }
    if (tid < 16)  { sc[tid] = bg[tid] * BNI; bi[tid] = bb[tid]; }
    const float* xb = x + b * 16384;
    int oy0 = ty * 16, ox0 = tx * 16;
    for (int idx = tid; idx < 324; idx += 256) {
        int ry = idx / 18, rx = idx % 18;
        int gy = oy0 - 1 + ry, gx = ox0 - 1 + rx;
        tile[idx] = (gy >= 0 && gy < 128 && gx >= 0 && gx < 128) ? xb[gy * 128 + gx] : 0.f;
    }
    __syncthreads();
    int py = threadIdx.y, px = threadIdx.x;
    float r[9];
#pragma unroll
    for (int dy = 0; dy < 3; dy++)
#pragma unroll
        for (int dx = 0; dx < 3; dx++)
            r[dy * 3 + dx] = tile[(py + dy) * 18 + px + dx];
    int ho = oy0 + py, wo = ox0 + px;
    float* out = g_h1 + (size_t)b * 16 * 16384 + ho * 128 + wo;
#pragma unroll
    for (int c = 0; c < 16; c++) {
        const float4* wv = (const float4*)(ws + c * 12);
        float4 w0 = wv[0], w1 = wv[1], w2 = wv[2];
        float v = w0.x * r[0] + w0.y * r[1] + w0.z * r[2] + w0.w * r[3]
                + w1.x * r[4] + w1.y * r[5] + w1.z * r[6] + w1.w * r[7]
                + w2.x * r[8];
        out[c * 16384] = fmaxf(v * sc[c] + bi[c], 0.f);
    }
}

// ---------------- SE pooling: mean over HW per (b,c) -----------------------
__global__ void pool_kernel(int stage) {
    const float* src; int HW; float inv;
    if (stage == 1)      { src = g_h1; HW = 16384; inv = 1.f / 16384.f; }
    else if (stage == 2) { src = g_h2; HW = 4096;  inv = 1.f / 4096.f; }
    else                 { src = g_h3; HW = 1024;  inv = 1.f / 1024.f; }
    int bc = blockIdx.x;
    const float* p = src + (size_t)bc * HW;
    float sum = 0.f;
    for (int i = threadIdx.x; i < HW; i += 256) sum += p[i];
    __shared__ float wp[8];
#pragma unroll
    for (int o = 16; o; o >>= 1) sum += __shfl_xor_sync(~0u, sum, o);
    if ((threadIdx.x & 31) == 0) wp[threadIdx.x >> 5] = sum;
    __syncthreads();
    if (threadIdx.x == 0) {
        float t = 0.f;
#pragma unroll
        for (int w = 0; w < 8; w++) t += wp[w];
        g_pool[bc] = t * inv;
    }
}

// ---------------- SE gate (tiny MLP) per batch -----------------------------
__global__ void gate_kernel(const float* __restrict__ w1, const float* __restrict__ b1,
                            const float* __restrict__ w2, const float* __restrict__ b2,
                            int C, int K) {
    int b = blockIdx.x, c = threadIdx.x;
    __shared__ float y[64], hid[8];
    y[c] = g_pool[b * C + c];
    __syncthreads();
    if (c < K) {
        float t = b1[c];
        for (int j = 0; j < C; j++) t += w1[c * C + j] * y[j];
        hid[c] = fmaxf(t, 0.f);
    }
    __syncthreads();
    float t = b2[c];
    for (int k = 0; k < K; k++) t += w2[c * K + k] * hid[k];
    g_gate[b * C + c] = 1.f / (1.f + expf(-t));
}

// ---------------- conv2: 16->32, s2, pad1, BN+ReLU, gated in compute -------
__global__ void __launch_bounds__(256) conv2_kernel(const float* __restrict__ w,
                                                    const float* __restrict__ bg,
                                                    const float* __restrict__ bb) {
    __shared__ float sin[2][4 * 1089];
    __shared__ __align__(16) float ws[2][1536];
    __shared__ float sc[32], bi[32], sg[16];
    int b = blockIdx.z, ty = blockIdx.y, tx = blockIdx.x;
    int tid = threadIdx.x;
    if (tid < 32) { sc[tid] = bg[tid] * BNI; bi[tid] = bb[tid]; }
    if (tid < 16) sg[tid] = g_gate[b * 16 + tid];
    int cg = tid >> 7, s = tid & 127;
    int row = s >> 3, c8 = s & 7;
    int iy0 = ty * 32 - 1, ix0 = tx * 32 - 1;
    const float* src = g_h1 + (size_t)b * 16 * 16384;

    float acc[32];
#pragma unroll
    for (int k = 0; k < 32; k++) acc[k] = 0.f;

    cpw_rows<32, 16>(tid, s2u(&ws[0][0]), w, 0);
    cpin_rows<4, 33, 33, 128, 128>(tid, s2u(&sin[0][0]), src, iy0, ix0);
    cp_commit();

    for (int ch = 0; ch < 4; ch++) {
        int buf = ch & 1;
        cp_wait<0>();
        __syncthreads();
        if (ch < 3) {
            int nb = buf ^ 1;
            cpw_rows<32, 16>(tid, s2u(&ws[nb][0]), w, (ch + 1) * 4);
            cpin_rows<4, 33, 33, 128, 128>(tid, s2u(&sin[nb][0]), src + (ch + 1) * 4 * 16384, iy0, ix0);
            cp_commit();
        }
#pragma unroll
        for (int ci = 0; ci < 4; ci++) {
            float g = sg[ch * 4 + ci];
            float rin[15];
            const float* ip = &sin[buf][ci * 1089 + (2 * row) * 33 + 4 * c8];
#pragma unroll
            for (int dy = 0; dy < 3; dy++)
#pragma unroll
                for (int dx = 0; dx < 5; dx++)
                    rin[dy * 5 + dx] = ip[dy * 33 + dx] * g;
            const float4* wp = (const float4*)&ws[buf][(ci * 32 + cg * 16) * 12];
#pragma unroll
            for (int co = 0; co < 16; co++) {
                float4 w0 = wp[co * 3], w1 = wp[co * 3 + 1], w2 = wp[co * 3 + 2];
                acc[co * 2]     += w0.x * rin[0]  + w0.y * rin[1]  + w0.z * rin[2]
                                 + w0.w * rin[5]  + w1.x * rin[6]  + w1.y * rin[7]
                                 + w1.z * rin[10] + w1.w * rin[11] + w2.x * rin[12];
                acc[co * 2 + 1] += w0.x * rin[2]  + w0.y * rin[3]  + w0.z * rin[4]
                                 + w0.w * rin[7]  + w1.x * rin[8]  + w1.y * rin[9]
                                 + w1.z * rin[12] + w1.w * rin[13] + w2.x * rin[14];
            }
        }
    }
    int ho = ty * 16 + row, wo = tx * 16 + 2 * c8;
    float* out = g_h2 + (size_t)b * 32 * 4096 + ho * 64 + wo;
#pragma unroll
    for (int co = 0; co < 16; co++) {
        int cog = cg * 16 + co;
        out[cog * 4096]     = fmaxf(acc[co * 2]     * sc[cog] + bi[cog], 0.f);
        out[cog * 4096 + 1] = fmaxf(acc[co * 2 + 1] * sc[cog] + bi[cog], 0.f);
    }
}

// ---------------- conv3: 32->64, s2, pad1, BN+ReLU, gated in compute -------
__global__ void __launch_bounds__(256) conv3_kernel(const float* __restrict__ w,
                                                    const float* __restrict__ bg,
                                                    const float* __restrict__ bb) {
    __shared__ float sin[2][4 * 561];
    __shared__ __align__(16) float ws[2][3072];
    __shared__ float sc[64], bi[64], sg[32];
    int b = blockIdx.z, ty = blockIdx.y, tx = blockIdx.x;
    int tid = threadIdx.x;
    if (tid < 64) { sc[tid] = bg[tid] * BNI; bi[tid] = bb[tid]; }
    if (tid < 32) sg[tid] = g_gate[b * 32 + tid];
    int cg = tid >> 6, s = tid & 63;
    int row = s >> 2, c4 = s & 3;
    int iy0 = ty * 32 - 1, ix0 = tx * 16 - 1;
    const float* src = g_h2 + (size_t)b * 32 * 4096;

    float acc[32];
#pragma unroll
    for (int k = 0; k < 32; k++) acc[k] = 0.f;

    cpw_rows<64, 32>(tid, s2u(&ws[0][0]), w, 0);
    cpin_rows<4, 33, 17, 64, 64>(tid, s2u(&sin[0][0]), src, iy0, ix0);
    cp_commit();

    for (int ch = 0; ch < 8; ch++) {
        int buf = ch & 1;
        cp_wait<0>();
        __syncthreads();
        if (ch < 7) {
            int nb = buf ^ 1;
            cpw_rows<64, 32>(tid, s2u(&ws[nb][0]), w, (ch + 1) * 4);
            cpin_rows<4, 33, 17, 64, 64>(tid, s2u(&sin[nb][0]), src + (ch + 1) * 4 * 4096, iy0, ix0);
            cp_commit();
        }
#pragma unroll
        for (int ci = 0; ci < 4; ci++) {
            float g = sg[ch * 4 + ci];
            float rin[15];
            const float* ip = &sin[buf][ci * 561 + (2 * row) * 17 + 4 * c4];
#pragma unroll
            for (int dy = 0; dy < 3; dy++)
#pragma unroll
                for (int dx = 0; dx < 5; dx++)
                    rin[dy * 5 + dx] = ip[dy * 17 + dx] * g;
            const float4* wp = (const float4*)&ws[buf][(ci * 64 + cg * 16) * 12];
#pragma unroll
            for (int co = 0; co < 16; co++) {
                float4 w0 = wp[co * 3], w1 = wp[co * 3 + 1], w2 = wp[co * 3 + 2];
                acc[co * 2]     += w0.x * rin[0]  + w0.y * rin[1]  + w0.z * rin[2]
                                 + w0.w * rin[5]  + w1.x * rin[6]  + w1.y * rin[7]
                                 + w1.z * rin[10] + w1.w * rin[11] + w2.x * rin[12];
                acc[co * 2 + 1] += w0.x * rin[2]  + w0.y * rin[3]  + w0.z * rin[4]
                                 + w0.w * rin[7]  + w1.x * rin[8]  + w1.y * rin[9]
                                 + w1.z * rin[12] + w1.w * rin[13] + w2.x * rin[14];
            }
        }
    }
    int ho = ty * 16 + row, wo = tx * 8 + 2 * c4;
#pragma unroll
    for (int co = 0; co < 16; co++) {
        int cog = cg * 16 + co;
        float* out = g_h3 + ((size_t)b * 64 + cog) * 1024 + ho * 32 + wo;
        out[0] = fmaxf(acc[co * 2]     * sc[cog] + bi[cog], 0.f);
        out[1] = fmaxf(acc[co * 2 + 1] * sc[cog] + bi[cog], 0.f);
    }
}

// ------ primary caps: 64->64, s2, pad1, +bias, gated in compute, squash ----
__global__ void __launch_bounds__(256) pc_kernel(const float* __restrict__ w,
                                                 const float* __restrict__ pb) {
    __shared__ float sin[2][4 * 1089];
    __shared__ __align__(16) float ws[2][1536];
    __shared__ float sbias[32], sg[64];
    int H = blockIdx.x, b = blockIdx.y;
    int tid = threadIdx.x;
    if (tid < 32) sbias[tid] = pb[H * 32 + tid];
    if (tid < 64) sg[tid] = g_gate[b * 64 + tid];
    int cg = tid >> 7, s = tid & 127;
    int row = s >> 3, c8 = s & 7;
    const float* src = g_h3 + (size_t)b * 64 * 1024;
    const float* wbase = w + (size_t)(H * 32) * 576;   // [co_l][64][9]

    float acc[32];
#pragma unroll
    for (int k = 0; k < 32; k++) acc[k] = 0.f;

    cpw_rows<32, 64>(tid, s2u(&ws[0][0]), wbase, 0);
    cpin_rows<4, 33, 33, 32, 32>(tid, s2u(&sin[0][0]), src, -1, -1);
    cp_commit();

    for (int ch = 0; ch < 16; ch++) {
        int buf = ch & 1;
        cp_wait<0>();
        __syncthreads();
        if (ch < 15) {
            int nb = buf ^ 1;
            cpw_rows<32, 64>(tid, s2u(&ws[nb][0]), wbase, (ch + 1) * 4);
            cpin_rows<4, 33, 33, 32, 32>(tid, s2u(&sin[nb][0]), src + (ch + 1) * 4 * 1024, -1, -1);
            cp_commit();
        }
#pragma unroll
        for (int ci = 0; ci < 4; ci++) {
            float g = sg[ch * 4 + ci];
            float rin[15];
            const float* ip = &sin[buf][ci * 1089 + (2 * row) * 33 + 4 * c8];
#pragma unroll
            for (int dy = 0; dy < 3; dy++)
#pragma unroll
                for (int dx = 0; dx < 5; dx++)
                    rin[dy * 5 + dx] = ip[dy * 33 + dx] * g;
            const float4* wp = (const float4*)&ws[buf][(ci * 32 + cg * 16) * 12];
#pragma unroll
            for (int co = 0; co < 16; co++) {
                float4 w0 = wp[co * 3], w1 = wp[co * 3 + 1], w2 = wp[co * 3 + 2];
                acc[co * 2]     += w0.x * rin[0]  + w0.y * rin[1]  + w0.z * rin[2]
                                 + w0.w * rin[5]  + w1.x * rin[6]  + w1.y * rin[7]
                                 + w1.z * rin[10] + w1.w * rin[11] + w2.x * rin[12];
                acc[co * 2 + 1] += w0.x * rin[2]  + w0.y * rin[3]  + w0.z * rin[4]
                                 + w0.w * rin[7]  + w1.x * rin[8]  + w1.y * rin[9]
                                 + w1.z * rin[12] + w1.w * rin[13] + w2.x * rin[14];
            }
        }
    }
#pragma unroll
    for (int co = 0; co < 16; co++) {
        float bsv = sbias[cg * 16 + co];
        acc[co * 2] += bsv; acc[co * 2 + 1] += bsv;
    }
    // co_glob = H*32 + cg*16 + 8a + e ; a0 = H*4 + cg*2 + a
#pragma unroll
    for (int a = 0; a < 2; a++)
#pragma unroll
        for (int px = 0; px < 2; px++) {
            float n2 = 0.f;
#pragma unroll
            for (int e = 0; e < 8; e++) {
                float v = acc[(a * 8 + e) * 2 + px];
                n2 += v * v;
            }
            float f = (n2 / (1.f + n2)) / (sqrtf(n2) + 1e-8f);
            int i = (H * 4 + cg * 2 + a) * 256 + row * 16 + 2 * c8 + px;
            float* up = g_u + ((size_t)b * 2048 + i) * 8;
#pragma unroll
            for (int e = 0; e < 8; e++)
                up[e] = acc[(a * 8 + e) * 2 + px] * f;
        }
}

// ---------------- u_hat[b,i,c,d] = sum_e W[i,c,d,e] * u[b,i,e] -------------
__global__ void uhat_kernel(const float* __restrict__ W) {
    int idx = blockIdx.x * 256 + threadIdx.x;
    int b = idx / 98304;
    int r = idx - b * 98304;
    int i = r / 48;
    const float4* wp = (const float4*)(W + (size_t)r * 8);
    const float4* up = (const float4*)(g_u + ((size_t)b * 2048 + i) * 8);
    float4 w0 = wp[0], w1 = wp[1], u0 = up[0], u1 = up[1];
    g_uhat[idx] = w0.x * u0.x + w0.y * u0.y + w0.z * u0.z + w0.w * u0.w
                + w1.x * u1.x + w1.y * u1.y + w1.z * u1.z + w1.w * u1.w;
}

// ---------------- dynamic routing (exact Round-1 version) ------------------
__device__ __forceinline__ void reduce_squash(float* sacc, float mult,
                                              float* s, float* v, float* wpart,
                                              int tid, int lane, int wid) {
#pragma unroll
    for (int k = 0; k < 48; k++) {
        float x = sacc[k];
#pragma unroll
        for (int o = 16; o; o >>= 1) x += __shfl_xor_sync(~0u, x, o);
        if (lane == 0) wpart[wid * 48 + k] = x;
    }
    __syncthreads();
    if (tid < 48) {
        float t = 0.f;
#pragma unroll
        for (int w = 0; w < 8; w++) t += wpart[w * 48 + tid];
        s[tid] = t * mult;
    }
    __syncthreads();
    if (tid < 3) {
        float n2 = 0.f;
#pragma unroll
        for (int d = 0; d < 16; d++) n2 += s[tid * 16 + d] * s[tid * 16 + d];
        float f = (n2 / (1.f + n2)) / (sqrtf(n2) + 1e-8f);
#pragma unroll
        for (int d = 0; d < 16; d++) v[tid * 16 + d] = s[tid * 16 + d] * f;
    }
    __syncthreads();
}

__global__ void __launch_bounds__(256) routing_kernel(float* __restrict__ out) {
    __shared__ float bl[2048 * 3];
    __shared__ float s[48], v[48];
    __shared__ float wpart[8 * 48];
    int b = blockIdx.x, tid = threadIdx.x, lane = tid & 31, wid = tid >> 5;
    const float* uh_b = g_uhat + (size_t)b * 98304;
    for (int idx = tid; idx < 6144; idx += 256) bl[idx] = 0.f;
    __syncthreads();

    float sacc[48];
#pragma unroll
    for (int k = 0; k < 48; k++) sacc[k] = 0.f;
    for (int r = 0; r < 8; r++) {
        int i = r * 256 + tid;
        const float4* p = (const float4*)(uh_b + i * 48);
#pragma unroll
        for (int q = 0; q < 12; q++) {
            float4 t = p[q];
            sacc[4 * q] += t.x; sacc[4 * q + 1] += t.y;
            sacc[4 * q + 2] += t.z; sacc[4 * q + 3] += t.w;
        }
    }
    reduce_squash(sacc, 1.f / 3.f, s, v, wpart, tid, lane, wid);

    for (int it = 1; it < 3; it++) {
#pragma unroll
        for (int k = 0; k < 48; k++) sacc[k] = 0.f;
        for (int r = 0; r < 8; r++) {
            int i = r * 256 + tid;
            const float4* p = (const float4*)(uh_b + i * 48);
            float uh[48];
#pragma unroll
            for (int q = 0; q < 12; q++) {
                float4 t = p[q];
                uh[4 * q] = t.x; uh[4 * q + 1] = t.y;
                uh[4 * q + 2] = t.z; uh[4 * q + 3] = t.w;
            }
            float a0 = 0.f, a1 = 0.f, a2 = 0.f;
#pragma unroll
            for (int d = 0; d < 16; d++) {
                a0 += uh[d] * v[d];
                a1 += uh[16 + d] * v[16 + d];
                a2 += uh[32 + d] * v[32 + d];
            }
            float b0 = bl[i * 3] + a0, b1 = bl[i * 3 + 1] + a1, b2 = bl[i * 3 + 2] + a2;
            bl[i * 3] = b0; bl[i * 3 + 1] = b1; bl[i * 3 + 2] = b2;
            float m = fmaxf(b0, fmaxf(b1, b2));
            float e0 = expf(b0 - m), e1 = expf(b1 - m), e2 = expf(b2 - m);
            float inv = 1.f / (e0 + e1 + e2);
            e0 *= inv; e1 *= inv; e2 *= inv;
#pragma unroll
            for (int d = 0; d < 16; d++) {
                sacc[d]      += e0 * uh[d];
                sacc[16 + d] += e1 * uh[16 + d];
                sacc[32 + d] += e2 * uh[32 + d];
            }
        }
        reduce_squash(sacc, 1.f, s, v, wpart, tid, lane, wid);
    }

    if (tid < 3) {
        float n2 = 0.f;
#pragma unroll
        for (int d = 0; d < 16; d++) n2 += v[tid * 16 + d] * v[tid * 16 + d];
        out[b * 3 + tid] = sqrtf(n2);
    }
}

// ---------------------------------------------------------------------------
extern "C" void kernel_launch(void* const* d_in, const int* in_sizes, int n_in,
                              void* d_out, int out_size) {
    const float* x       = (const float*)d_in[0];
    const float* conv1_w = (const float*)d_in[1];
    const float* bn1_g   = (const float*)d_in[2];
    const float* bn1_b   = (const float*)d_in[3];
    const float* se1_w1  = (const float*)d_in[4];
    const float* se1_b1  = (const float*)d_in[5];
    const float* se1_w2  = (const float*)d_in[6];
    const float* se1_b2  = (const float*)d_in[7];
    const float* conv2_w = (const float*)d_in[8];
    const float* bn2_g   = (const float*)d_in[9];
    const float* bn2_b   = (const float*)d_in[10];
    const float* se2_w1  = (const float*)d_in[11];
    const float* se2_b1  = (const float*)d_in[12];
    const float* se2_w2  = (const float*)d_in[13];
    const float* se2_b2  = (const float*)d_in[14];
    const float* conv3_w = (const float*)d_in[15];
    const float* bn3_g   = (const float*)d_in[16];
    const float* bn3_b   = (const float*)d_in[17];
    const float* se3_w1  = (const float*)d_in[18];
    const float* se3_b1  = (const float*)d_in[19];
    const float* se3_w2  = (const float*)d_in[20];
    const float* se3_b2  = (const float*)d_in[21];
    const float* pc_w    = (const float*)d_in[22];
    const float* pc_b    = (const float*)d_in[23];
    const float* W_digit = (const float*)d_in[24];
    float* out = (float*)d_out;

    conv1_kernel<<<dim3(8, 8, 64), dim3(16, 16)>>>(x, conv1_w, bn1_g, bn1_b);
    pool_kernel<<<64 * 16, 256>>>(1);
    gate_kernel<<<64, 16>>>(se1_w1, se1_b1, se1_w2, se1_b2, 16, 1);
    conv2_kernel<<<dim3(4, 4, 64), 256>>>(conv2_w, bn2_g, bn2_b);
    pool_kernel<<<64 * 32, 256>>>(2);
    gate_kernel<<<64, 32>>>(se2_w1, se2_b1, se2_w2, se2_b2, 32, 2);
    conv3_kernel<<<dim3(4, 2, 64), 256>>>(conv3_w, bn3_g, bn3_b);
    pool_kernel<<<64 * 64, 256>>>(3);
    gate_kernel<<<64, 64>>>(se3_w1, se3_b1, se3_w2, se3_b2, 64, 4);
    pc_kernel<<<dim3(2, 64), 256>>>(pc_w, pc_b);
    uhat_kernel<<<24576, 256>>>(W_digit);
    routing_kernel<<<64, 256>>>(out);
}

// round 12
// speedup vs baseline: 1.5053x; 1.4997x over previous
#include <cuda_runtime.h>
#include <math.h>

#define BNI 0.9999950000374997f   // 1/sqrt(1+1e-5)

// ---------------- scratch (device globals; identical set to Round 1) -------
__device__ float g_h1[64 * 16 * 128 * 128];
__device__ float g_h2[64 * 32 * 64 * 64];
__device__ float g_h3[64 * 64 * 32 * 32];
__device__ float g_u [64 * 2048 * 8];
__device__ float g_uhat[64 * 2048 * 48];
__device__ float g_pool[64 * 64];
__device__ float g_gate[64 * 64];

// ---------------- cp.async helpers -----------------------------------------
__device__ __forceinline__ unsigned int s2u(const void* p) {
    return (unsigned int)__cvta_generic_to_shared(p);
}
__device__ __forceinline__ void cpa4(unsigned int d, const float* s, bool ok) {
    int n = ok ? 4 : 0;
    asm volatile("cp.async.ca.shared.global [%0], [%1], 4, %2;" :: "r"(d), "l"(s), "r"(n));
}
__device__ __forceinline__ void cpa16(unsigned int d, const float* s, bool ok) {
    int n = ok ? 16 : 0;
    asm volatile("cp.async.cg.shared.global [%0], [%1], 16, %2;" :: "r"(d), "l"(s), "r"(n));
}
__device__ __forceinline__ void cp_commit() { asm volatile("cp.async.commit_group;"); }
template<int N> __device__ __forceinline__ void cp_wait() {
    asm volatile("cp.async.wait_group %0;" :: "n"(N));
}

// vectorized input tile copy: NCI planes of TH rows x TWV float4s.
// window origin ix0a is 16B-aligned; vectors are uniformly in/out of bounds.
// flat-idx strided loop (proven low-register form).
template<int NCI, int TH, int TWV, int H, int W>
__device__ __forceinline__ void cpin_vec(int tid, unsigned int din,
                                         const float* __restrict__ src,
                                         int iy0, int ix0a) {
    const int RV = TH * TWV;
    const int TOT = NCI * RV;
    for (int idx = tid; idx < TOT; idx += 256) {
        int ci = idx / RV, r = idx - ci * RV;
        int ry = r / TWV, v = r - ry * TWV;
        int gy = iy0 + ry, gx0 = ix0a + 4 * v;
        bool ok = (gy >= 0) & (gy < H) & (gx0 >= 0) & (gx0 < W);
        cpa16(din + idx * 16,
              src + ci * (H * W) + (ok ? gy : 0) * W + (ok ? gx0 : 0), ok);
    }
}

// weight chunk copy, 12-padded: dst [ci_l][co][12]; src [co][CIT][9]
template<int NCI, int NCO, int CIT>
__device__ __forceinline__ void cpw_chunk(int tid, unsigned int dw,
                                          const float* __restrict__ wbase, int ci0) {
    const int TOT = NCI * NCO * 12;
    for (int idx = tid; idx < TOT; idx += 256) {
        int q = idx / 12, k = idx - q * 12;
        int ci_l = q / NCO, co = q - ci_l * NCO;
        bool ok = k < 9;
        cpa4(dw + idx * 4, wbase + co * (CIT * 9) + (ci0 + ci_l) * 9 + (ok ? k : 0), ok);
    }
}

// ---------------- conv1: 1->16, stride 1, pad 1, BN+ReLU -------------------
__global__ void conv1_kernel(const float* __restrict__ x,
                             const float* __restrict__ w,
                             const float* __restrict__ bg,
                             const float* __restrict__ bb) {
    __shared__ float tile[18 * 18];
    __shared__ __align__(16) float ws[16 * 12];
    __shared__ float sc[16], bi[16];
    int b = blockIdx.z, ty = blockIdx.y, tx = blockIdx.x;
    int tid = threadIdx.y * 16 + threadIdx.x;
    if (tid < 144) { int c = tid / 9, k = tid % 9; ws[c * 12 + k] = w[tid]; }
    if (tid < 16)  { sc[tid] = bg[tid] * BNI; bi[tid] = bb[tid]; }
    const float* xb = x + b * 16384;
    int oy0 = ty * 16, ox0 = tx * 16;
    for (int idx = tid; idx < 324; idx += 256) {
        int ry = idx / 18, rx = idx % 18;
        int gy = oy0 - 1 + ry, gx = ox0 - 1 + rx;
        tile[idx] = (gy >= 0 && gy < 128 && gx >= 0 && gx < 128) ? xb[gy * 128 + gx] : 0.f;
    }
    __syncthreads();
    int py = threadIdx.y, px = threadIdx.x;
    float r[9];
#pragma unroll
    for (int dy = 0; dy < 3; dy++)
#pragma unroll
        for (int dx = 0; dx < 3; dx++)
            r[dy * 3 + dx] = tile[(py + dy) * 18 + px + dx];
    int ho = oy0 + py, wo = ox0 + px;
    float* out = g_h1 + (size_t)b * 16 * 16384 + ho * 128 + wo;
#pragma unroll
    for (int c = 0; c < 16; c++) {
        const float4* wv = (const float4*)(ws + c * 12);
        float4 w0 = wv[0], w1 = wv[1], w2 = wv[2];
        float v = w0.x * r[0] + w0.y * r[1] + w0.z * r[2] + w0.w * r[3]
                + w1.x * r[4] + w1.y * r[5] + w1.z * r[6] + w1.w * r[7]
                + w2.x * r[8];
        out[c * 16384] = fmaxf(v * sc[c] + bi[c], 0.f);
    }
}

// ---------------- SE pooling: mean over HW per (b,c) -----------------------
__global__ void pool_kernel(int stage) {
    const float* src; int HW; float inv;
    if (stage == 1)      { src = g_h1; HW = 16384; inv = 1.f / 16384.f; }
    else if (stage == 2) { src = g_h2; HW = 4096;  inv = 1.f / 4096.f; }
    else                 { src = g_h3; HW = 1024;  inv = 1.f / 1024.f; }
    int bc = blockIdx.x;
    const float* p = src + (size_t)bc * HW;
    float sum = 0.f;
    for (int i = threadIdx.x; i < HW; i += 256) sum += p[i];
    __shared__ float wp[8];
#pragma unroll
    for (int o = 16; o; o >>= 1) sum += __shfl_xor_sync(~0u, sum, o);
    if ((threadIdx.x & 31) == 0) wp[threadIdx.x >> 5] = sum;
    __syncthreads();
    if (threadIdx.x == 0) {
        float t = 0.f;
#pragma unroll
        for (int w = 0; w < 8; w++) t += wp[w];
        g_pool[bc] = t * inv;
    }
}

// ---------------- SE gate (tiny MLP) per batch -----------------------------
__global__ void gate_kernel(const float* __restrict__ w1, const float* __restrict__ b1,
                            const float* __restrict__ w2, const float* __restrict__ b2,
                            int C, int K) {
    int b = blockIdx.x, c = threadIdx.x;
    __shared__ float y[64], hid[8];
    y[c] = g_pool[b * C + c];
    __syncthreads();
    if (c < K) {
        float t = b1[c];
        for (int j = 0; j < C; j++) t += w1[c * C + j] * y[j];
        hid[c] = fmaxf(t, 0.f);
    }
    __syncthreads();
    float t = b2[c];
    for (int k = 0; k < K; k++) t += w2[c * K + k] * hid[k];
    g_gate[b * C + c] = 1.f / (1.f + expf(-t));
}

// ---------------- conv2: 16->32, s2, pad1, BN+ReLU, gated in compute -------
// 2-ci chunks x 8; aligned 36-wide tile (compute offset +3).
__global__ void __launch_bounds__(256) conv2_kernel(const float* __restrict__ w,
                                                    const float* __restrict__ bg,
                                                    const float* __restrict__ bb) {
    __shared__ __align__(16) float sin[2][2 * 33 * 36];
    __shared__ __align__(16) float ws[2][768];
    __shared__ float sc[32], bi[32], sg[16];
    int b = blockIdx.z, ty = blockIdx.y, tx = blockIdx.x;
    int tid = threadIdx.x;
    if (tid < 32) { sc[tid] = bg[tid] * BNI; bi[tid] = bb[tid]; }
    if (tid < 16) sg[tid] = g_gate[b * 16 + tid];
    int cg = tid >> 7, s = tid & 127;
    int row = s >> 3, c8 = s & 7;
    int iy0 = ty * 32 - 1, ix0a = tx * 32 - 4;
    const float* src = g_h1 + (size_t)b * 16 * 16384;

    float acc[32];
#pragma unroll
    for (int k = 0; k < 32; k++) acc[k] = 0.f;

    cpw_chunk<2, 32, 16>(tid, s2u(&ws[0][0]), w, 0);
    cpin_vec<2, 33, 9, 128, 128>(tid, s2u(&sin[0][0]), src, iy0, ix0a);
    cp_commit();

    for (int ch = 0; ch < 8; ch++) {
        int buf = ch & 1;
        cp_wait<0>();
        __syncthreads();
        if (ch < 7) {
            int nb = buf ^ 1;
            cpw_chunk<2, 32, 16>(tid, s2u(&ws[nb][0]), w, (ch + 1) * 2);
            cpin_vec<2, 33, 9, 128, 128>(tid, s2u(&sin[nb][0]), src + (ch + 1) * 2 * 16384, iy0, ix0a);
            cp_commit();
        }
#pragma unroll
        for (int ci = 0; ci < 2; ci++) {
            float g = sg[ch * 2 + ci];
            float rin[15];
            const float* ip = &sin[buf][ci * 1188 + (2 * row) * 36 + 3 + 4 * c8];
#pragma unroll
            for (int dy = 0; dy < 3; dy++)
#pragma unroll
                for (int dx = 0; dx < 5; dx++)
                    rin[dy * 5 + dx] = ip[dy * 36 + dx] * g;
            const float4* wp = (const float4*)&ws[buf][(ci * 32 + cg * 16) * 12];
#pragma unroll
            for (int co = 0; co < 16; co++) {
                float4 w0 = wp[co * 3], w1 = wp[co * 3 + 1], w2 = wp[co * 3 + 2];
                acc[co * 2]     += w0.x * rin[0]  + w0.y * rin[1]  + w0.z * rin[2]
                                 + w0.w * rin[5]  + w1.x * rin[6]  + w1.y * rin[7]
                                 + w1.z * rin[10] + w1.w * rin[11] + w2.x * rin[12];
                acc[co * 2 + 1] += w0.x * rin[2]  + w0.y * rin[3]  + w0.z * rin[4]
                                 + w0.w * rin[7]  + w1.x * rin[8]  + w1.y * rin[9]
                                 + w1.z * rin[12] + w1.w * rin[13] + w2.x * rin[14];
            }
        }
    }
    int ho = ty * 16 + row, wo = tx * 16 + 2 * c8;
    float* out = g_h2 + (size_t)b * 32 * 4096 + ho * 64 + wo;
#pragma unroll
    for (int co = 0; co < 16; co++) {
        int cog = cg * 16 + co;
        out[cog * 4096]     = fmaxf(acc[co * 2]     * sc[cog] + bi[cog], 0.f);
        out[cog * 4096 + 1] = fmaxf(acc[co * 2 + 1] * sc[cog] + bi[cog], 0.f);
    }
}

// ---------------- conv3: 32->64, s2, pad1, BN+ReLU, gated in compute -------
// 4-ci chunks x 8; aligned 20-wide tile (compute offset +3).
__global__ void __launch_bounds__(256) conv3_kernel(const float* __restrict__ w,
                                                    const float* __restrict__ bg,
                                                    const float* __restrict__ bb) {
    __shared__ __align__(16) float sin[2][4 * 33 * 20];
    __shared__ __align__(16) float ws[2][3072];
    __shared__ float sc[64], bi[64], sg[32];
    int b = blockIdx.z, ty = blockIdx.y, tx = blockIdx.x;
    int tid = threadIdx.x;
    if (tid < 64) { sc[tid] = bg[tid] * BNI; bi[tid] = bb[tid]; }
    if (tid < 32) sg[tid] = g_gate[b * 32 + tid];
    int cg = tid >> 6, s = tid & 63;
    int row = s >> 2, c4 = s & 3;
    int iy0 = ty * 32 - 1, ix0a = tx * 16 - 4;
    const float* src = g_h2 + (size_t)b * 32 * 4096;

    float acc[32];
#pragma unroll
    for (int k = 0; k < 32; k++) acc[k] = 0.f;

    cpw_chunk<4, 64, 32>(tid, s2u(&ws[0][0]), w, 0);
    cpin_vec<4, 33, 5, 64, 64>(tid, s2u(&sin[0][0]), src, iy0, ix0a);
    cp_commit();

    for (int ch = 0; ch < 8; ch++) {
        int buf = ch & 1;
        cp_wait<0>();
        __syncthreads();
        if (ch < 7) {
            int nb = buf ^ 1;
            cpw_chunk<4, 64, 32>(tid, s2u(&ws[nb][0]), w, (ch + 1) * 4);
            cpin_vec<4, 33, 5, 64, 64>(tid, s2u(&sin[nb][0]), src + (ch + 1) * 4 * 4096, iy0, ix0a);
            cp_commit();
        }
#pragma unroll
        for (int ci = 0; ci < 4; ci++) {
            float g = sg[ch * 4 + ci];
            float rin[15];
            const float* ip = &sin[buf][ci * 660 + (2 * row) * 20 + 3 + 4 * c4];
#pragma unroll
            for (int dy = 0; dy < 3; dy++)
#pragma unroll
                for (int dx = 0; dx < 5; dx++)
                    rin[dy * 5 + dx] = ip[dy * 20 + dx] * g;
            const float4* wp = (const float4*)&ws[buf][(ci * 64 + cg * 16) * 12];
#pragma unroll
            for (int co = 0; co < 16; co++) {
                float4 w0 = wp[co * 3], w1 = wp[co * 3 + 1], w2 = wp[co * 3 + 2];
                acc[co * 2]     += w0.x * rin[0]  + w0.y * rin[1]  + w0.z * rin[2]
                                 + w0.w * rin[5]  + w1.x * rin[6]  + w1.y * rin[7]
                                 + w1.z * rin[10] + w1.w * rin[11] + w2.x * rin[12];
                acc[co * 2 + 1] += w0.x * rin[2]  + w0.y * rin[3]  + w0.z * rin[4]
                                 + w0.w * rin[7]  + w1.x * rin[8]  + w1.y * rin[9]
                                 + w1.z * rin[12] + w1.w * rin[13] + w2.x * rin[14];
            }
        }
    }
    int ho = ty * 16 + row, wo = tx * 8 + 2 * c4;
#pragma unroll
    for (int co = 0; co < 16; co++) {
        int cog = cg * 16 + co;
        float* out = g_h3 + ((size_t)b * 64 + cog) * 1024 + ho * 32 + wo;
        out[0] = fmaxf(acc[co * 2]     * sc[cog] + bi[cog], 0.f);
        out[1] = fmaxf(acc[co * 2 + 1] * sc[cog] + bi[cog], 0.f);
    }
}

// ------ primary caps: 64->64, s2, pad1, +bias, gated in compute, squash ----
// 2-ci chunks x 32; aligned 36-wide tile.
__global__ void __launch_bounds__(256) pc_kernel(const float* __restrict__ w,
                                                 const float* __restrict__ pb) {
    __shared__ __align__(16) float sin[2][2 * 33 * 36];
    __shared__ __align__(16) float ws[2][768];
    __shared__ float sbias[32], sg[64];
    int H = blockIdx.x, b = blockIdx.y;
    int tid = threadIdx.x;
    if (tid < 32) sbias[tid] = pb[H * 32 + tid];
    if (tid < 64) sg[tid] = g_gate[b * 64 + tid];
    int cg = tid >> 7, s = tid & 127;
    int row = s >> 3, c8 = s & 7;
    const float* src = g_h3 + (size_t)b * 64 * 1024;
    const float* wbase = w + (size_t)(H * 32) * 576;   // [co_l][64][9]

    float acc[32];
#pragma unroll
    for (int k = 0; k < 32; k++) acc[k] = 0.f;

    cpw_chunk<2, 32, 64>(tid, s2u(&ws[0][0]), wbase, 0);
    cpin_vec<2, 33, 9, 32, 32>(tid, s2u(&sin[0][0]), src, -1, -4);
    cp_commit();

    for (int ch = 0; ch < 32; ch++) {
        int buf = ch & 1;
        cp_wait<0>();
        __syncthreads();
        if (ch < 31) {
            int nb = buf ^ 1;
            cpw_chunk<2, 32, 64>(tid, s2u(&ws[nb][0]), wbase, (ch + 1) * 2);
            cpin_vec<2, 33, 9, 32, 32>(tid, s2u(&sin[nb][0]), src + (ch + 1) * 2 * 1024, -1, -4);
            cp_commit();
        }
#pragma unroll
        for (int ci = 0; ci < 2; ci++) {
            float g = sg[ch * 2 + ci];
            float rin[15];
            const float* ip = &sin[buf][ci * 1188 + (2 * row) * 36 + 3 + 4 * c8];
#pragma unroll
            for (int dy = 0; dy < 3; dy++)
#pragma unroll
                for (int dx = 0; dx < 5; dx++)
                    rin[dy * 5 + dx] = ip[dy * 36 + dx] * g;
            const float4* wp = (const float4*)&ws[buf][(ci * 32 + cg * 16) * 12];
#pragma unroll
            for (int co = 0; co < 16; co++) {
                float4 w0 = wp[co * 3], w1 = wp[co * 3 + 1], w2 = wp[co * 3 + 2];
                acc[co * 2]     += w0.x * rin[0]  + w0.y * rin[1]  + w0.z * rin[2]
                                 + w0.w * rin[5]  + w1.x * rin[6]  + w1.y * rin[7]
                                 + w1.z * rin[10] + w1.w * rin[11] + w2.x * rin[12];
                acc[co * 2 + 1] += w0.x * rin[2]  + w0.y * rin[3]  + w0.z * rin[4]
                                 + w0.w * rin[7]  + w1.x * rin[8]  + w1.y * rin[9]
                                 + w1.z * rin[12] + w1.w * rin[13] + w2.x * rin[14];
            }
        }
    }
#pragma unroll
    for (int co = 0; co < 16; co++) {
        float bsv = sbias[cg * 16 + co];
        acc[co * 2] += bsv; acc[co * 2 + 1] += bsv;
    }
    // co_glob = H*32 + cg*16 + 8a + e ; a0 = H*4 + cg*2 + a
#pragma unroll
    for (int a = 0; a < 2; a++)
#pragma unroll
        for (int px = 0; px < 2; px++) {
            float n2 = 0.f;
#pragma unroll
            for (int e = 0; e < 8; e++) {
                float v = acc[(a * 8 + e) * 2 + px];
                n2 += v * v;
            }
            float f = (n2 / (1.f + n2)) / (sqrtf(n2) + 1e-8f);
            int i = (H * 4 + cg * 2 + a) * 256 + row * 16 + 2 * c8 + px;
            float* up = g_u + ((size_t)b * 2048 + i) * 8;
#pragma unroll
            for (int e = 0; e < 8; e++)
                up[e] = acc[(a * 8 + e) * 2 + px] * f;
        }
}

// ---------------- u_hat[b,i,c,d] = sum_e W[i,c,d,e] * u[b,i,e] -------------
__global__ void uhat_kernel(const float* __restrict__ W) {
    int idx = blockIdx.x * 256 + threadIdx.x;
    int b = idx / 98304;
    int r = idx - b * 98304;
    int i = r / 48;
    const float4* wp = (const float4*)(W + (size_t)r * 8);
    const float4* up = (const float4*)(g_u + ((size_t)b * 2048 + i) * 8);
    float4 w0 = wp[0], w1 = wp[1], u0 = up[0], u1 = up[1];
    g_uhat[idx] = w0.x * u0.x + w0.y * u0.y + w0.z * u0.z + w0.w * u0.w
                + w1.x * u1.x + w1.y * u1.y + w1.z * u1.z + w1.w * u1.w;
}

// ---------------- dynamic routing (exact Round-1 version) ------------------
__device__ __forceinline__ void reduce_squash(float* sacc, float mult,
                                              float* s, float* v, float* wpart,
                                              int tid, int lane, int wid) {
#pragma unroll
    for (int k = 0; k < 48; k++) {
        float x = sacc[k];
#pragma unroll
        for (int o = 16; o; o >>= 1) x += __shfl_xor_sync(~0u, x, o);
        if (lane == 0) wpart[wid * 48 + k] = x;
    }
    __syncthreads();
    if (tid < 48) {
        float t = 0.f;
#pragma unroll
        for (int w = 0; w < 8; w++) t += wpart[w * 48 + tid];
        s[tid] = t * mult;
    }
    __syncthreads();
    if (tid < 3) {
        float n2 = 0.f;
#pragma unroll
        for (int d = 0; d < 16; d++) n2 += s[tid * 16 + d] * s[tid * 16 + d];
        float f = (n2 / (1.f + n2)) / (sqrtf(n2) + 1e-8f);
#pragma unroll
        for (int d = 0; d < 16; d++) v[tid * 16 + d] = s[tid * 16 + d] * f;
    }
    __syncthreads();
}

__global__ void __launch_bounds__(256) routing_kernel(float* __restrict__ out) {
    __shared__ float bl[2048 * 3];
    __shared__ float s[48], v[48];
    __shared__ float wpart[8 * 48];
    int b = blockIdx.x, tid = threadIdx.x, lane = tid & 31, wid = tid >> 5;
    const float* uh_b = g_uhat + (size_t)b * 98304;
    for (int idx = tid; idx < 6144; idx += 256) bl[idx] = 0.f;
    __syncthreads();

    float sacc[48];
#pragma unroll
    for (int k = 0; k < 48; k++) sacc[k] = 0.f;
    for (int r = 0; r < 8; r++) {
        int i = r * 256 + tid;
        const float4* p = (const float4*)(uh_b + i * 48);
#pragma unroll
        for (int q = 0; q < 12; q++) {
            float4 t = p[q];
            sacc[4 * q] += t.x; sacc[4 * q + 1] += t.y;
            sacc[4 * q + 2] += t.z; sacc[4 * q + 3] += t.w;
        }
    }
    reduce_squash(sacc, 1.f / 3.f, s, v, wpart, tid, lane, wid);

    for (int it = 1; it < 3; it++) {
#pragma unroll
        for (int k = 0; k < 48; k++) sacc[k] = 0.f;
        for (int r = 0; r < 8; r++) {
            int i = r * 256 + tid;
            const float4* p = (const float4*)(uh_b + i * 48);
            float uh[48];
#pragma unroll
            for (int q = 0; q < 12; q++) {
                float4 t = p[q];
                uh[4 * q] = t.x; uh[4 * q + 1] = t.y;
                uh[4 * q + 2] = t.z; uh[4 * q + 3] = t.w;
            }
            float a0 = 0.f, a1 = 0.f, a2 = 0.f;
#pragma unroll
            for (int d = 0; d < 16; d++) {
                a0 += uh[d] * v[d];
                a1 += uh[16 + d] * v[16 + d];
                a2 += uh[32 + d] * v[32 + d];
            }
            float b0 = bl[i * 3] + a0, b1 = bl[i * 3 + 1] + a1, b2 = bl[i * 3 + 2] + a2;
            bl[i * 3] = b0; bl[i * 3 + 1] = b1; bl[i * 3 + 2] = b2;
            float m = fmaxf(b0, fmaxf(b1, b2));
            float e0 = expf(b0 - m), e1 = expf(b1 - m), e2 = expf(b2 - m);
            float inv = 1.f / (e0 + e1 + e2);
            e0 *= inv; e1 *= inv; e2 *= inv;
#pragma unroll
            for (int d = 0; d < 16; d++) {
                sacc[d]      += e0 * uh[d];
                sacc[16 + d] += e1 * uh[16 + d];
                sacc[32 + d] += e2 * uh[32 + d];
            }
        }
        reduce_squash(sacc, 1.f, s, v, wpart, tid, lane, wid);
    }

    if (tid < 3) {
        float n2 = 0.f;
#pragma unroll
        for (int d = 0; d < 16; d++) n2 += v[tid * 16 + d] * v[tid * 16 + d];
        out[b * 3 + tid] = sqrtf(n2);
    }
}

// ---------------------------------------------------------------------------
extern "C" void kernel_launch(void* const* d_in, const int* in_sizes, int n_in,
                              void* d_out, int out_size) {
    const float* x       = (const float*)d_in[0];
    const float* conv1_w = (const float*)d_in[1];
    const float* bn1_g   = (const float*)d_in[2];
    const float* bn1_b   = (const float*)d_in[3];
    const float* se1_w1  = (const float*)d_in[4];
    const float* se1_b1  = (const float*)d_in[5];
    const float* se1_w2  = (const float*)d_in[6];
    const float* se1_b2  = (const float*)d_in[7];
    const float* conv2_w = (const float*)d_in[8];
    const float* bn2_g   = (const float*)d_in[9];
    const float* bn2_b   = (const float*)d_in[10];
    const float* se2_w1  = (const float*)d_in[11];
    const float* se2_b1  = (const float*)d_in[12];
    const float* se2_w2  = (const float*)d_in[13];
    const float* se2_b2  = (const float*)d_in[14];
    const float* conv3_w = (const float*)d_in[15];
    const float* bn3_g   = (const float*)d_in[16];
    const float* bn3_b   = (const float*)d_in[17];
    const float* se3_w1  = (const float*)d_in[18];
    const float* se3_b1  = (const float*)d_in[19];
    const float* se3_w2  = (const float*)d_in[20];
    const float* se3_b2  = (const float*)d_in[21];
    const float* pc_w    = (const float*)d_in[22];
    const float* pc_b    = (const float*)d_in[23];
    const float* W_digit = (const float*)d_in[24];
    float* out = (float*)d_out;

    conv1_kernel<<<dim3(8, 8, 64), dim3(16, 16)>>>(x, conv1_w, bn1_g, bn1_b);
    pool_kernel<<<64 * 16, 256>>>(1);
    gate_kernel<<<64, 16>>>(se1_w1, se1_b1, se1_w2, se1_b2, 16, 1);
    conv2_kernel<<<dim3(4, 4, 64), 256>>>(conv2_w, bn2_g, bn2_b);
    pool_kernel<<<64 * 32, 256>>>(2);
    gate_kernel<<<64, 32>>>(se2_w1, se2_b1, se2_w2, se2_b2, 32, 2);
    conv3_kernel<<<dim3(4, 2, 64), 256>>>(conv3_w, bn3_g, bn3_b);
    pool_kernel<<<64 * 64, 256>>>(3);
    gate_kernel<<<64, 64>>>(se3_w1, se3_b1, se3_w2, se3_b2, 64, 4);
    pc_kernel<<<dim3(2, 64), 256>>>(pc_w, pc_b);
    uhat_kernel<<<24576, 256>>>(W_digit);
    routing_kernel<<<64, 256>>>(out);
}